// round 13
// baseline (speedup 1.0000x reference)
#include <cuda_runtime.h>
#include <math.h>

#define BATCH 8
#define T1 50176
#define T2 12544
#define T3 3136
#define EMB 64
#define MDIM 32
#define D2 576
#define M2TOT (BATCH * T2)   // 100352
#define M3TOT (BATCH * T3)   // 25088

__device__ float g_kp1[BATCH * T1 * MDIM];
__device__ float g_qp1[BATCH * T1 * MDIM];
__device__ float g_v1 [BATCH * T1 * EMB];
__device__ float g_ks1[BATCH * MDIM];
__device__ float g_kptv1[BATCH * EMB * MDIM];
__device__ float g_x1 [BATCH * EMB * T1];
__device__ float g_feat2T[(size_t)D2 * M2TOT];   // [e][token] K-major
__device__ float g_kqv2[BATCH * T2 * 192];
__device__ float g_kp2[BATCH * T2 * MDIM];
__device__ float g_qp2[BATCH * T2 * MDIM];
__device__ float g_ks2[BATCH * MDIM];
__device__ float g_kptv2[BATCH * EMB * MDIM];
__device__ float g_x2 [BATCH * EMB * T2];
__device__ float g_feat3T[(size_t)D2 * M3TOT];   // [e][token] K-major

// ---------------- f32x2 packed helpers ----------------
__device__ __forceinline__ unsigned long long pk2(float lo, float hi) {
    unsigned long long r;
    asm("mov.b64 %0, {%1,%2};" : "=l"(r) : "f"(lo), "f"(hi));
    return r;
}
__device__ __forceinline__ void fma2(unsigned long long& d, unsigned long long a,
                                     unsigned long long b) {
    asm("fma.rn.f32x2 %0, %1, %2, %0;" : "+l"(d) : "l"(a), "l"(b));
}
__device__ __forceinline__ float2 upk(unsigned long long v) {
    float2 r;
    asm("mov.b64 {%0,%1}, %2;" : "=f"(r.x), "=f"(r.y) : "l"(v));
    return r;
}

__device__ __forceinline__ float warp_sum(float v) {
#pragma unroll
    for (int o = 16; o > 0; o >>= 1) v += __shfl_xor_sync(0xffffffffu, v, o);
    return v;
}
__device__ __forceinline__ float red16(float v) {
    v += __shfl_xor_sync(0xffffffffu, v, 1);
    v += __shfl_xor_sync(0xffffffffu, v, 2);
    v += __shfl_xor_sync(0xffffffffu, v, 4);
    v += __shfl_xor_sync(0xffffffffu, v, 8);
    return v;
}

__global__ void zero_red_kernel() {
    int i = blockIdx.x * 256 + threadIdx.x;
    if (i < BATCH * MDIM) { g_ks1[i] = 0.f; g_ks2[i] = 0.f; }
    if (i < BATCH * EMB * MDIM) { g_kptv1[i] = 0.f; g_kptv2[i] = 0.f; }
}

__device__ __forceinline__ float dot28(const float* __restrict__ wp_,
                                       const unsigned long long* __restrict__ h2) {
    unsigned long long acc2 = 0;
#pragma unroll
    for (int e2 = 0; e2 < 7; e2++) {
        float4 wv = *(const float4*)&wp_[e2 * 4];
        fma2(acc2, h2[2 * e2],     pk2(wv.x, wv.y));
        fma2(acc2, h2[2 * e2 + 1], pk2(wv.z, wv.w));
    }
    float2 r = upk(acc2);
    return r.x + r.y;
}

// stage-1: unfold(s1) + LN(27) + kqv + phi(k,q); one thread per token
__global__ void __launch_bounds__(128) s1_pass1_kernel(
    const float* __restrict__ x, const float* __restrict__ kqv_w,
    const float* __restrict__ kqv_b, const float* __restrict__ n1g,
    const float* __restrict__ n1b, const float* __restrict__ w)
{
    __shared__ float s_kw[192 * 28];
    __shared__ float s_kb[192];
    __shared__ float s_wT[64 * MDIM];
    __shared__ float s_g[27], s_b[27];
    int tid = threadIdx.x;
    for (int i = tid; i < 192 * 28; i += 128) {
        int j = i / 28, e = i - j * 28;
        s_kw[i] = (e < 27) ? kqv_w[j * 27 + e] : 0.0f;
    }
    for (int i = tid; i < 192; i += 128) s_kb[i] = kqv_b[i];
    for (int i = tid; i < 64 * MDIM; i += 128) {
        int j = i >> 5, m = i & 31;
        s_wT[i] = w[m * 64 + j];
    }
    if (tid < 27) { s_g[tid] = n1g[tid]; s_b[tid] = n1b[tid]; }
    __syncthreads();

    int gt = blockIdx.x * 128 + tid;
    int b  = gt / T1;
    int hw = gt - b * T1;
    int hh = hw / 224, ww = hw - hh * 224;
    const float* xb = x + (size_t)b * 3 * T1;

    float f[27];
#pragma unroll
    for (int c = 0; c < 3; c++)
#pragma unroll
        for (int kh = 0; kh < 3; kh++)
#pragma unroll
            for (int kw2 = 0; kw2 < 3; kw2++) {
                int yy = hh + kh - 1, xx = ww + kw2 - 1;
                float v = 0.0f;
                if ((unsigned)yy < 224u && (unsigned)xx < 224u)
                    v = xb[(c * 224 + yy) * 224 + xx];
                f[c * 9 + kh * 3 + kw2] = v;
            }
    float mu = 0.f;
#pragma unroll
    for (int e = 0; e < 27; e++) mu += f[e];
    mu *= (1.0f / 27.0f);
    float var = 0.f;
#pragma unroll
    for (int e = 0; e < 27; e++) { float d = f[e] - mu; var += d * d; }
    var *= (1.0f / 27.0f);
    float rs = rsqrtf(var + 1e-5f);
    float h[28];
#pragma unroll
    for (int e = 0; e < 27; e++) h[e] = (f[e] - mu) * rs * s_g[e] + s_b[e];
    h[27] = 0.f;
    unsigned long long h2[14];
#pragma unroll
    for (int e = 0; e < 14; e++) h2[e] = pk2(h[2 * e], h[2 * e + 1]);

    const float scm = 0.17677669529663687f;
#pragma unroll
    for (int ph = 0; ph < 2; ph++) {
        unsigned long long wtx2[16];
#pragma unroll
        for (int m = 0; m < 16; m++) wtx2[m] = 0;
        float nrm = 0.f;
        for (int j = 0; j < 64; j++) {
            int row = ph * 64 + j;
            float acc = s_kb[row] + dot28(&s_kw[row * 28], h2);
            nrm += acc * acc;
            unsigned long long ad = pk2(acc, acc);
            const float* wr = &s_wT[j * MDIM];
#pragma unroll
            for (int m4 = 0; m4 < 8; m4++) {
                float4 wv = *(const float4*)&wr[m4 * 4];
                fma2(wtx2[m4 * 2],     ad, pk2(wv.x, wv.y));
                fma2(wtx2[m4 * 2 + 1], ad, pk2(wv.z, wv.w));
            }
        }
        float hn = 0.5f * nrm;
        float* outp = (ph == 0 ? g_kp1 : g_qp1) + (size_t)gt * MDIM;
#pragma unroll
        for (int m2 = 0; m2 < 16; m2++) {
            float2 p = upk(wtx2[m2]);
            outp[2 * m2]     = expf(p.x - hn) * scm;
            outp[2 * m2 + 1] = expf(p.y - hn) * scm;
        }
    }
    float* vout = g_v1 + (size_t)gt * EMB;
    for (int j = 0; j < 64; j++)
        vout[j] = s_kb[128 + j] + dot28(&s_kw[(128 + j) * 28], h2);
}

// ks[m] = sum_t kp[t][m]; kptv[n][m] = sum_t v[t][n]*kp[t][m]; 448 tokens/block
__global__ void __launch_bounds__(256) reduce_kernel(int stage, int T, int vstride)
{
    const float* kp = stage ? g_kp2 : g_kp1;
    const float* v  = stage ? (g_kqv2 + 128) : g_v1;
    float* ks   = stage ? g_ks2 : g_ks1;
    float* kptv = stage ? g_kptv2 : g_kptv1;

    __shared__ float s_kp[16 * MDIM];
    __shared__ float s_v [16 * EMB];
    int b = blockIdx.y, tid = threadIdx.x;
    int tok0 = blockIdx.x * 448;
    int n = tid >> 2, m0 = (tid & 3) * 8;
    float acc[8];
#pragma unroll
    for (int i = 0; i < 8; i++) acc[i] = 0.f;
    float ksacc = 0.f;
    const float* kpb = kp + ((size_t)b * T) * MDIM;
    const float* vb  = v  + ((size_t)b * T) * (size_t)vstride;
    for (int tile = 0; tile < 28; tile++) {
        int tb = tok0 + tile * 16;
        for (int i = tid; i < 16 * MDIM; i += 256)
            s_kp[i] = kpb[(size_t)tb * MDIM + i];
        for (int i = tid; i < 16 * EMB; i += 256) {
            int tt = i >> 6, nn = i & 63;
            s_v[i] = vb[(size_t)(tb + tt) * vstride + nn];
        }
        __syncthreads();
        if (tid < 32) {
#pragma unroll
            for (int tt = 0; tt < 16; tt++) ksacc += s_kp[tt * MDIM + tid];
        }
#pragma unroll 4
        for (int tt = 0; tt < 16; tt++) {
            float vv = s_v[tt * EMB + n];
#pragma unroll
            for (int i = 0; i < 8; i++) acc[i] += vv * s_kp[tt * MDIM + m0 + i];
        }
        __syncthreads();
    }
#pragma unroll
    for (int i = 0; i < 8; i++)
        atomicAdd(&kptv[b * EMB * MDIM + n * MDIM + m0 + i], acc[i]);
    if (tid < 32) atomicAdd(&ks[b * MDIM + tid], ksacc);
}

// performer epilogue: block-tiled GEMMs, f32x2-packed along token pairs
__global__ void __launch_bounds__(256, 2) pass2_kernel(
    int stage, int T, int vstride,
    const float* __restrict__ pw, const float* __restrict__ pb,
    const float* __restrict__ g2v, const float* __restrict__ b2v,
    const float* __restrict__ m1w, const float* __restrict__ m1b,
    const float* __restrict__ m2w, const float* __restrict__ m2b)
{
    const float* qp   = stage ? g_qp2 : g_qp1;
    const float* v    = stage ? (g_kqv2 + 128) : g_v1;
    const float* ksg  = stage ? g_ks2 : g_ks1;
    const float* kptv = stage ? g_kptv2 : g_kptv1;
    float* xout       = stage ? g_x2 : g_x1;

    extern __shared__ float sm[];
    float* s_w1   = sm;
    float* s_w2   = sm + 4352;
    float* s_w3   = sm + 8704;
    float* s_kptv = sm + 13056;
    float* s_Q    = sm + 15232;
    float* s_V    = sm + 17344;
    float* s_X    = sm + 21696;
    float* s_ks   = sm + 25920;
    float* s_pb   = sm + 25952;
    float* s_g2   = sm + 26016;
    float* s_b2   = sm + 26080;
    float* s_m1b  = sm + 26144;
    float* s_m2b  = sm + 26208;

    int b = blockIdx.y, tid = threadIdx.x;
    int tx = tid & 15, ty = tid >> 4;
    int t0 = ty * 4, c0 = tx * 4;

    for (int idx = tid; idx < 4096; idx += 256) {
        int n = idx >> 6, j = idx & 63;
        s_w1[j * 68 + n] = pw [idx];
        s_w2[j * 68 + n] = m1w[idx];
        s_w3[j * 68 + n] = m2w[idx];
    }
    for (int idx = tid; idx < 2048; idx += 256) {
        int n = idx >> 5, m = idx & 31;
        s_kptv[m * 68 + n] = kptv[b * 2048 + idx];
    }
    if (tid < 32) s_ks[tid] = ksg[b * 32 + tid];
    if (tid < 64) {
        s_pb[tid] = pb[tid]; s_g2[tid] = g2v[tid]; s_b2[tid] = b2v[tid];
        s_m1b[tid] = m1b[tid]; s_m2b[tid] = m2b[tid];
    }
    __syncthreads();

    int nchunks = T >> 6;
    for (int chunk = blockIdx.x; chunk < nchunks; chunk += gridDim.x) {
        int tbase = chunk << 6;
        {
            const float* qb = qp + ((size_t)b * T + tbase) * MDIM;
            for (int idx = tid; idx < 2048; idx += 256) {
                int t = idx >> 5, m = idx & 31;
                s_Q[m * 66 + t] = qb[idx];
            }
        }
        {
            const float* vb = v + ((size_t)b * T + tbase) * (size_t)vstride;
            for (int idx = tid; idx < 1024; idx += 256) {
                int t = idx >> 4, cc = (idx & 15) * 4;
                float4 val = *(const float4*)&vb[(size_t)t * vstride + cc];
                *(float4*)&s_V[t * 68 + cc] = val;
            }
        }
        __syncthreads();

        unsigned long long a1acc[2][4], dv2[2];
        dv2[0] = dv2[1] = 0;
#pragma unroll
        for (int p = 0; p < 2; p++)
#pragma unroll
            for (int j = 0; j < 4; j++) a1acc[p][j] = 0;
#pragma unroll
        for (int kk = 0; kk < 32; kk++) {
            float2 a01 = *(const float2*)&s_Q[kk * 66 + t0];
            float2 a23 = *(const float2*)&s_Q[kk * 66 + t0 + 2];
            unsigned long long ap0 = pk2(a01.x, a01.y);
            unsigned long long ap1 = pk2(a23.x, a23.y);
            float4 bv = *(const float4*)&s_kptv[kk * 68 + c0];
            float kse = s_ks[kk];
            unsigned long long ksd = pk2(kse, kse);
            fma2(dv2[0], ap0, ksd); fma2(dv2[1], ap1, ksd);
            unsigned long long b0 = pk2(bv.x, bv.x), b1 = pk2(bv.y, bv.y);
            unsigned long long b2 = pk2(bv.z, bv.z), b3 = pk2(bv.w, bv.w);
            fma2(a1acc[0][0], ap0, b0); fma2(a1acc[0][1], ap0, b1);
            fma2(a1acc[0][2], ap0, b2); fma2(a1acc[0][3], ap0, b3);
            fma2(a1acc[1][0], ap1, b0); fma2(a1acc[1][1], ap1, b1);
            fma2(a1acc[1][2], ap1, b2); fma2(a1acc[1][3], ap1, b3);
        }
#pragma unroll
        for (int p = 0; p < 2; p++) {
            float2 dd = upk(dv2[p]);
            float inv0 = 1.0f / (dd.x + 1e-8f);
            float inv1 = 1.0f / (dd.y + 1e-8f);
#pragma unroll
            for (int j = 0; j < 4; j++) {
                float2 yy = upk(a1acc[p][j]);
                s_X[(c0 + j) * 66 + t0 + 2 * p]     = yy.x * inv0;
                s_X[(c0 + j) * 66 + t0 + 2 * p + 1] = yy.y * inv1;
            }
        }
        __syncthreads();

        unsigned long long o2[2][4];
#pragma unroll
        for (int p = 0; p < 2; p++)
#pragma unroll
            for (int j = 0; j < 4; j++)
                o2[p][j] = pk2(s_V[(t0 + 2 * p) * 68 + c0 + j] + s_pb[c0 + j],
                               s_V[(t0 + 2 * p + 1) * 68 + c0 + j] + s_pb[c0 + j]);
#pragma unroll
        for (int kk = 0; kk < 64; kk++) {
            float2 a01 = *(const float2*)&s_X[kk * 66 + t0];
            float2 a23 = *(const float2*)&s_X[kk * 66 + t0 + 2];
            unsigned long long ap0 = pk2(a01.x, a01.y);
            unsigned long long ap1 = pk2(a23.x, a23.y);
            float4 bv = *(const float4*)&s_w1[kk * 68 + c0];
            unsigned long long b0 = pk2(bv.x, bv.x), b1 = pk2(bv.y, bv.y);
            unsigned long long b2 = pk2(bv.z, bv.z), b3 = pk2(bv.w, bv.w);
            fma2(o2[0][0], ap0, b0); fma2(o2[0][1], ap0, b1);
            fma2(o2[0][2], ap0, b2); fma2(o2[0][3], ap0, b3);
            fma2(o2[1][0], ap1, b0); fma2(o2[1][1], ap1, b1);
            fma2(o2[1][2], ap1, b2); fma2(o2[1][3], ap1, b3);
        }
        float o[4][4];
#pragma unroll
        for (int p = 0; p < 2; p++)
#pragma unroll
            for (int j = 0; j < 4; j++) {
                float2 val = upk(o2[p][j]);
                o[2 * p][j] = val.x;
                o[2 * p + 1][j] = val.y;
            }
        float hh[4][4];
#pragma unroll
        for (int i = 0; i < 4; i++) {
            float s = red16(o[i][0] + o[i][1] + o[i][2] + o[i][3]);
            float mu = s * (1.0f / 64.0f);
            float d0 = o[i][0] - mu, d1 = o[i][1] - mu;
            float d2 = o[i][2] - mu, d3 = o[i][3] - mu;
            float vs = red16(d0 * d0 + d1 * d1 + d2 * d2 + d3 * d3);
            float rsl = rsqrtf(vs * (1.0f / 64.0f) + 1e-5f);
            hh[i][0] = d0 * rsl * s_g2[c0 + 0] + s_b2[c0 + 0];
            hh[i][1] = d1 * rsl * s_g2[c0 + 1] + s_b2[c0 + 1];
            hh[i][2] = d2 * rsl * s_g2[c0 + 2] + s_b2[c0 + 2];
            hh[i][3] = d3 * rsl * s_g2[c0 + 3] + s_b2[c0 + 3];
        }
        __syncthreads();
#pragma unroll
        for (int i = 0; i < 4; i++)
#pragma unroll
            for (int j = 0; j < 4; j++)
                s_X[(c0 + j) * 66 + t0 + i] = hh[i][j];
        __syncthreads();

        unsigned long long u2[2][4];
#pragma unroll
        for (int p = 0; p < 2; p++)
#pragma unroll
            for (int j = 0; j < 4; j++)
                u2[p][j] = pk2(s_m1b[c0 + j], s_m1b[c0 + j]);
#pragma unroll
        for (int kk = 0; kk < 64; kk++) {
            float2 a01 = *(const float2*)&s_X[kk * 66 + t0];
            float2 a23 = *(const float2*)&s_X[kk * 66 + t0 + 2];
            unsigned long long ap0 = pk2(a01.x, a01.y);
            unsigned long long ap1 = pk2(a23.x, a23.y);
            float4 bv = *(const float4*)&s_w2[kk * 68 + c0];
            unsigned long long b0 = pk2(bv.x, bv.x), b1 = pk2(bv.y, bv.y);
            unsigned long long b2 = pk2(bv.z, bv.z), b3 = pk2(bv.w, bv.w);
            fma2(u2[0][0], ap0, b0); fma2(u2[0][1], ap0, b1);
            fma2(u2[0][2], ap0, b2); fma2(u2[0][3], ap0, b3);
            fma2(u2[1][0], ap1, b0); fma2(u2[1][1], ap1, b1);
            fma2(u2[1][2], ap1, b2); fma2(u2[1][3], ap1, b3);
        }
        __syncthreads();
#pragma unroll
        for (int p = 0; p < 2; p++)
#pragma unroll
            for (int j = 0; j < 4; j++) {
                float2 uu = upk(u2[p][j]);
                float g0 = 0.5f * uu.x * (1.0f + erff(uu.x * 0.70710678118654752f));
                float g1 = 0.5f * uu.y * (1.0f + erff(uu.y * 0.70710678118654752f));
                s_X[(c0 + j) * 66 + t0 + 2 * p]     = g0;
                s_X[(c0 + j) * 66 + t0 + 2 * p + 1] = g1;
            }
        __syncthreads();

        unsigned long long r2[2][4];
#pragma unroll
        for (int p = 0; p < 2; p++)
#pragma unroll
            for (int j = 0; j < 4; j++)
                r2[p][j] = pk2(o[2 * p][j] + s_m2b[c0 + j],
                               o[2 * p + 1][j] + s_m2b[c0 + j]);
#pragma unroll
        for (int kk = 0; kk < 64; kk++) {
            float2 a01 = *(const float2*)&s_X[kk * 66 + t0];
            float2 a23 = *(const float2*)&s_X[kk * 66 + t0 + 2];
            unsigned long long ap0 = pk2(a01.x, a01.y);
            unsigned long long ap1 = pk2(a23.x, a23.y);
            float4 bv = *(const float4*)&s_w3[kk * 68 + c0];
            unsigned long long b0 = pk2(bv.x, bv.x), b1 = pk2(bv.y, bv.y);
            unsigned long long b2 = pk2(bv.z, bv.z), b3 = pk2(bv.w, bv.w);
            fma2(r2[0][0], ap0, b0); fma2(r2[0][1], ap0, b1);
            fma2(r2[0][2], ap0, b2); fma2(r2[0][3], ap0, b3);
            fma2(r2[1][0], ap1, b0); fma2(r2[1][1], ap1, b1);
            fma2(r2[1][2], ap1, b2); fma2(r2[1][3], ap1, b3);
        }
        __syncthreads();
#pragma unroll
        for (int p = 0; p < 2; p++)
#pragma unroll
            for (int j = 0; j < 4; j++) {
                float2 rr = upk(r2[p][j]);
                s_V[(c0 + j) * 68 + t0 + 2 * p]     = rr.x;
                s_V[(c0 + j) * 68 + t0 + 2 * p + 1] = rr.y;
            }
        __syncthreads();
        {
            float* xo = xout + (size_t)(b * 64) * T + tbase;
            for (int idx = tid; idx < 1024; idx += 256) {
                int cc = idx >> 4, t4 = (idx & 15) * 4;
                *(float4*)&xo[(size_t)cc * T + t4] = *(const float4*)&s_V[cc * 68 + t4];
            }
        }
        __syncthreads();
    }
}

// stage-2 tokens: unfold(s2 of x1) + LN(576) -> g_feat2T [e][token]
__global__ void __launch_bounds__(256) feat2_kernel(
    const float* __restrict__ g, const float* __restrict__ bb)
{
    __shared__ float s_g[D2], s_b[D2];
    int tid = threadIdx.x;
    for (int i = tid; i < D2; i += 256) { s_g[i] = g[i]; s_b[i] = bb[i]; }
    __syncthreads();

    int b = blockIdx.y;
    int t = blockIdx.x * 256 + tid;
    int i = t / 112, j = t - i * 112;
    const float* xb = g_x1 + (size_t)b * 64 * T1;
    int y0 = 2 * i - 1, x0 = 2 * j - 1;

    float s = 0.f, s2 = 0.f;
    for (int c = 0; c < 64; c++) {
        const float* cb = xb + (size_t)c * T1;
#pragma unroll
        for (int kh = 0; kh < 3; kh++) {
            int yy = y0 + kh;
            bool yok = (unsigned)yy < 224u;
            const float* rp = cb + yy * 224;
#pragma unroll
            for (int kw = 0; kw < 3; kw++) {
                int xx = x0 + kw;
                float v = (yok && (unsigned)xx < 224u) ? rp[xx] : 0.f;
                s += v; s2 += v * v;
            }
        }
    }
    float mu = s * (1.0f / 576.0f);
    float var = s2 * (1.0f / 576.0f) - mu * mu;
    float rs = rsqrtf(var + 1e-5f);

    float* outc = g_feat2T + (size_t)b * T2 + t;
    int e = 0;
    for (int c = 0; c < 64; c++) {
        const float* cb = xb + (size_t)c * T1;
#pragma unroll
        for (int kh = 0; kh < 3; kh++) {
            int yy = y0 + kh;
            bool yok = (unsigned)yy < 224u;
            const float* rp = cb + yy * 224;
#pragma unroll
            for (int kw = 0; kw < 3; kw++) {
                int xx = x0 + kw;
                float v = (yok && (unsigned)xx < 224u) ? rp[xx] : 0.f;
                outc[(size_t)e * M2TOT] = (v - mu) * rs * s_g[e] + s_b[e];
                e++;
            }
        }
    }
}

// K-major GEMM: A stored [K][Mtot]; W [N][K]; C[M][N] += bias
// 128x64 tile, 8x4 micro, f32x2, k-tile 32
__global__ void __launch_bounds__(256) gemm_kernel(
    int which, const float* __restrict__ W, const float* __restrict__ bias,
    float* __restrict__ outp, int N, int K)
{
    const float* AT = which ? g_feat3T : g_feat2T;
    int Mtot = which ? M3TOT : M2TOT;
    float* C = which ? outp : g_kqv2;

    __shared__ float As[32][132];
    __shared__ float Bs[32][68];
    int m0 = blockIdx.x * 128, n0 = blockIdx.y * 64;
    int tid = threadIdx.x;
    int tx = tid & 15, ty = tid >> 4;
    int arow = tid >> 2;
    int kq = (tid & 3) * 4;

    const float* Wp = W + (size_t)(n0 + arow) * K + kq;

    unsigned long long acc[4][4];
#pragma unroll
    for (int i = 0; i < 4; i++)
#pragma unroll
        for (int j = 0; j < 4; j++) acc[i][j] = 0;

    float4 areg[4];
#pragma unroll
    for (int q = 0; q < 4; q++) {
        int f = tid + q * 256;
        int krow = f >> 5, mc = f & 31;
        areg[q] = *(const float4*)&AT[(size_t)krow * Mtot + m0 + mc * 4];
    }
    float4 wva = *(const float4*)Wp;
    float4 wvb = *(const float4*)(Wp + 16);

    int nkt = K / 32;
    for (int kt = 0; kt < nkt; kt++) {
#pragma unroll
        for (int q = 0; q < 4; q++) {
            int f = tid + q * 256;
            int krow = f >> 5, mc = f & 31;
            *(float4*)&As[krow][mc * 4] = areg[q];
        }
        Bs[kq + 0][arow] = wva.x; Bs[kq + 1][arow] = wva.y;
        Bs[kq + 2][arow] = wva.z; Bs[kq + 3][arow] = wva.w;
        Bs[kq + 16][arow] = wvb.x; Bs[kq + 17][arow] = wvb.y;
        Bs[kq + 18][arow] = wvb.z; Bs[kq + 19][arow] = wvb.w;
        __syncthreads();
        if (kt + 1 < nkt) {
            int k0n = (kt + 1) * 32;
#pragma unroll
            for (int q = 0; q < 4; q++) {
                int f = tid + q * 256;
                int krow = f >> 5, mc = f & 31;
                areg[q] = *(const float4*)&AT[(size_t)(k0n + krow) * Mtot + m0 + mc * 4];
            }
            wva = *(const float4*)(Wp + k0n);
            wvb = *(const float4*)(Wp + k0n + 16);
        }
#pragma unroll
        for (int kk = 0; kk < 32; kk++) {
            float4 a0 = *(const float4*)&As[kk][ty * 8];
            float4 a1 = *(const float4*)&As[kk][ty * 8 + 4];
            float4 b  = *(const float4*)&Bs[kk][tx * 4];
            unsigned long long ap[4] = {pk2(a0.x, a0.y), pk2(a0.z, a0.w),
                                        pk2(a1.x, a1.y), pk2(a1.z, a1.w)};
            unsigned long long bd[4] = {pk2(b.x, b.x), pk2(b.y, b.y),
                                        pk2(b.z, b.z), pk2(b.w, b.w)};
#pragma unroll
            for (int i = 0; i < 4; i++) {
                fma2(acc[i][0], ap[i], bd[0]);
                fma2(acc[i][1], ap[i], bd[1]);
                fma2(acc[i][2], ap[i], bd[2]);
                fma2(acc[i][3], ap[i], bd[3]);
            }
        }
        __syncthreads();
    }
    float4 bb = *(const float4*)&bias[n0 + tx * 4];
#pragma unroll
    for (int i = 0; i < 4; i++) {
        float2 c0 = upk(acc[i][0]);
        float2 c1 = upk(acc[i][1]);
        float2 c2 = upk(acc[i][2]);
        float2 c3 = upk(acc[i][3]);
        int row = m0 + ty * 8 + 2 * i;
        float4 lo = {c0.x + bb.x, c1.x + bb.y, c2.x + bb.z, c3.x + bb.w};
        float4 hi = {c0.y + bb.x, c1.y + bb.y, c2.y + bb.z, c3.y + bb.w};
        *(float4*)&C[(size_t)row * N + n0 + tx * 4] = lo;
        *(float4*)&C[(size_t)(row + 1) * N + n0 + tx * 4] = hi;
    }
}

// stage-2 phi from kqv2 (warp per token)
__global__ void __launch_bounds__(256) phi2_kernel(const float* __restrict__ w)
{
    __shared__ float s_wT[64 * MDIM];
    int tid = threadIdx.x, lane = tid & 31, wp = tid >> 5;
    for (int i = tid; i < 64 * MDIM; i += 256) {
        int j = i >> 5, m = i & 31;
        s_wT[i] = w[m * 64 + j];
    }
    __syncthreads();
    int t = blockIdx.x * 8 + wp;
    const float* base = g_kqv2 + (size_t)t * 192;
    const float scm = 0.17677669529663687f;
#pragma unroll
    for (int ph = 0; ph < 2; ph++) {
        float k0 = base[ph * 64 + lane];
        float k1 = base[ph * 64 + 32 + lane];
        float nrm = warp_sum(k0 * k0 + k1 * k1);
        float acc = 0.f;
#pragma unroll
        for (int s = 0; s < 32; s++) {
            float a = __shfl_sync(0xffffffffu, k0, s);
            float b = __shfl_sync(0xffffffffu, k1, s);
            acc += a * s_wT[s * MDIM + lane] + b * s_wT[(s + 32) * MDIM + lane];
        }
        float val = expf(acc - 0.5f * nrm) * scm;
        float* outp = (ph == 0 ? g_kp2 : g_qp2);
        outp[(size_t)t * MDIM + lane] = val;
    }
}

// stage-3 gather: unfold(s2 of x2) -> g_feat3T [e][token]; thread per token
__global__ void __launch_bounds__(256) gather3_kernel()
{
    int gt = blockIdx.x * 256 + threadIdx.x;
    int b = gt / T3, t = gt - b * T3;
    int i = t / 56, j = t - i * 56;
    int y0 = 2 * i - 1, x0 = 2 * j - 1;
    const float* xb = g_x2 + (size_t)b * 64 * T2;
    float* outc = g_feat3T + gt;
    int e = 0;
    for (int c = 0; c < 64; c++) {
        const float* cb = xb + (size_t)c * T2;
#pragma unroll
        for (int kh = 0; kh < 3; kh++) {
            int yy = y0 + kh;
            bool yok = (unsigned)yy < 112u;
            const float* rp = cb + yy * 112;
#pragma unroll
            for (int kw = 0; kw < 3; kw++) {
                int xx = x0 + kw;
                float v = (yok && (unsigned)xx < 112u) ? rp[xx] : 0.f;
                outc[(size_t)e * M3TOT] = v;
                e++;
            }
        }
    }
}

extern "C" void kernel_launch(void* const* d_in, const int* in_sizes, int n_in,
                              void* d_out, int out_size)
{
    cudaFuncSetAttribute(pass2_kernel,
                         cudaFuncAttributeMaxDynamicSharedMemorySize, 105088);

    const float* x        = (const float*)d_in[0];
    const float* p1_kqv_w = (const float*)d_in[1];
    const float* p1_kqv_b = (const float*)d_in[2];
    const float* p1_pw    = (const float*)d_in[3];
    const float* p1_pb    = (const float*)d_in[4];
    const float* p1_n1g   = (const float*)d_in[5];
    const float* p1_n1b   = (const float*)d_in[6];
    const float* p1_n2g   = (const float*)d_in[7];
    const float* p1_n2b   = (const float*)d_in[8];
    const float* p1_m1w   = (const float*)d_in[9];
    const float* p1_m1b   = (const float*)d_in[10];
    const float* p1_m2w   = (const float*)d_in[11];
    const float* p1_m2b   = (const float*)d_in[12];
    const float* p1_w     = (const float*)d_in[13];
    const float* p2_kqv_w = (const float*)d_in[14];
    const float* p2_kqv_b = (const float*)d_in[15];
    const float* p2_pw    = (const float*)d_in[16];
    const float* p2_pb    = (const float*)d_in[17];
    const float* p2_n1g   = (const float*)d_in[18];
    const float* p2_n1b   = (const float*)d_in[19];
    const float* p2_n2g   = (const float*)d_in[20];
    const float* p2_n2b   = (const float*)d_in[21];
    const float* p2_m1w   = (const float*)d_in[22];
    const float* p2_m1b   = (const float*)d_in[23];
    const float* p2_m2w   = (const float*)d_in[24];
    const float* p2_m2b   = (const float*)d_in[25];
    const float* p2_w     = (const float*)d_in[26];
    const float* proj_w   = (const float*)d_in[27];
    const float* proj_b   = (const float*)d_in[28];
    float* out = (float*)d_out;

    zero_red_kernel<<<64, 256>>>();

    // stage 1
    s1_pass1_kernel<<<BATCH * T1 / 128, 128>>>(x, p1_kqv_w, p1_kqv_b,
                                               p1_n1g, p1_n1b, p1_w);
    reduce_kernel<<<dim3(T1 / 448, BATCH), 256>>>(0, T1, EMB);
    pass2_kernel<<<dim3(98, BATCH), 256, 105088>>>(0, T1, EMB,
        p1_pw, p1_pb, p1_n2g, p1_n2b, p1_m1w, p1_m1b, p1_m2w, p1_m2b);

    // stage 2
    feat2_kernel<<<dim3(T2 / 256, BATCH), 256>>>(p2_n1g, p2_n1b);
    gemm_kernel<<<dim3(M2TOT / 128, 192 / 64), 256>>>(
        0, p2_kqv_w, p2_kqv_b, nullptr, 192, D2);
    phi2_kernel<<<(BATCH * T2) / 8, 256>>>(p2_w);
    reduce_kernel<<<dim3(T2 / 448, BATCH), 256>>>(1, T2, 192);
    pass2_kernel<<<dim3(98, BATCH), 256, 105088>>>(1, T2, 192,
        p2_pw, p2_pb, p2_n2g, p2_n2b, p2_m1w, p2_m1b, p2_m2w, p2_m2b);

    // stage 3
    gather3_kernel<<<M3TOT / 256, 256>>>();
    gemm_kernel<<<dim3(M3TOT / 128, 768 / 64), 256>>>(
        1, proj_w, proj_b, out, 768, D2);
}

// round 15
// speedup vs baseline: 1.0677x; 1.0677x over previous
#include <cuda_runtime.h>
#include <math.h>

#define BATCH 8
#define T1 50176
#define T2 12544
#define T3 3136
#define EMB 64
#define MDIM 32
#define D2 576

__device__ float g_kp1[BATCH * T1 * MDIM];
__device__ float g_qp1[BATCH * T1 * MDIM];
__device__ float g_v1 [BATCH * T1 * EMB];
__device__ float g_ks1[BATCH * MDIM];
__device__ float g_kptv1[BATCH * EMB * MDIM];
__device__ float g_x1 [BATCH * EMB * T1];
__device__ float g_feat2[BATCH * T2 * D2];
__device__ float g_kqv2[BATCH * T2 * 192];
__device__ float g_kp2[BATCH * T2 * MDIM];
__device__ float g_qp2[BATCH * T2 * MDIM];
__device__ float g_ks2[BATCH * MDIM];
__device__ float g_kptv2[BATCH * EMB * MDIM];
__device__ float g_x2 [BATCH * EMB * T2];
__device__ float g_feat3[BATCH * T3 * D2];

// ---------------- f32x2 packed helpers ----------------
__device__ __forceinline__ unsigned long long pk2(float lo, float hi) {
    unsigned long long r;
    asm("mov.b64 %0, {%1,%2};" : "=l"(r) : "f"(lo), "f"(hi));
    return r;
}
__device__ __forceinline__ void fma2(unsigned long long& d, unsigned long long a,
                                     unsigned long long b) {
    asm("fma.rn.f32x2 %0, %1, %2, %0;" : "+l"(d) : "l"(a), "l"(b));
}
__device__ __forceinline__ float2 upk(unsigned long long v) {
    float2 r;
    asm("mov.b64 {%0,%1}, %2;" : "=f"(r.x), "=f"(r.y) : "l"(v));
    return r;
}

__device__ __forceinline__ float warp_sum(float v) {
#pragma unroll
    for (int o = 16; o > 0; o >>= 1) v += __shfl_xor_sync(0xffffffffu, v, o);
    return v;
}
__device__ __forceinline__ float red16(float v) {
    v += __shfl_xor_sync(0xffffffffu, v, 1);
    v += __shfl_xor_sync(0xffffffffu, v, 2);
    v += __shfl_xor_sync(0xffffffffu, v, 4);
    v += __shfl_xor_sync(0xffffffffu, v, 8);
    return v;
}

__global__ void zero_red_kernel() {
    int i = blockIdx.x * 256 + threadIdx.x;
    if (i < BATCH * MDIM) { g_ks1[i] = 0.f; g_ks2[i] = 0.f; }
    if (i < BATCH * EMB * MDIM) { g_kptv1[i] = 0.f; g_kptv2[i] = 0.f; }
}

__device__ __forceinline__ float dot28(const float* __restrict__ wp_,
                                       const unsigned long long* __restrict__ h2) {
    unsigned long long acc2 = 0;
#pragma unroll
    for (int e2 = 0; e2 < 7; e2++) {
        float4 wv = *(const float4*)&wp_[e2 * 4];
        fma2(acc2, h2[2 * e2],     pk2(wv.x, wv.y));
        fma2(acc2, h2[2 * e2 + 1], pk2(wv.z, wv.w));
    }
    float2 r = upk(acc2);
    return r.x + r.y;
}

// stage-1: unfold(s1) + LN(27) + kqv + phi(k,q); one thread per token
__global__ void __launch_bounds__(128) s1_pass1_kernel(
    const float* __restrict__ x, const float* __restrict__ kqv_w,
    const float* __restrict__ kqv_b, const float* __restrict__ n1g,
    const float* __restrict__ n1b, const float* __restrict__ w)
{
    __shared__ float s_kw[192 * 28];
    __shared__ float s_kb[192];
    __shared__ float s_wT[64 * MDIM];
    __shared__ float s_g[27], s_b[27];
    int tid = threadIdx.x;
    for (int i = tid; i < 192 * 28; i += 128) {
        int j = i / 28, e = i - j * 28;
        s_kw[i] = (e < 27) ? kqv_w[j * 27 + e] : 0.0f;
    }
    for (int i = tid; i < 192; i += 128) s_kb[i] = kqv_b[i];
    for (int i = tid; i < 64 * MDIM; i += 128) {
        int j = i >> 5, m = i & 31;
        s_wT[i] = w[m * 64 + j];
    }
    if (tid < 27) { s_g[tid] = n1g[tid]; s_b[tid] = n1b[tid]; }
    __syncthreads();

    int gt = blockIdx.x * 128 + tid;
    int b  = gt / T1;
    int hw = gt - b * T1;
    int hh = hw / 224, ww = hw - hh * 224;
    const float* xb = x + (size_t)b * 3 * T1;

    float f[27];
#pragma unroll
    for (int c = 0; c < 3; c++)
#pragma unroll
        for (int kh = 0; kh < 3; kh++)
#pragma unroll
            for (int kw2 = 0; kw2 < 3; kw2++) {
                int yy = hh + kh - 1, xx = ww + kw2 - 1;
                float v = 0.0f;
                if ((unsigned)yy < 224u && (unsigned)xx < 224u)
                    v = xb[(c * 224 + yy) * 224 + xx];
                f[c * 9 + kh * 3 + kw2] = v;
            }
    float mu = 0.f;
#pragma unroll
    for (int e = 0; e < 27; e++) mu += f[e];
    mu *= (1.0f / 27.0f);
    float var = 0.f;
#pragma unroll
    for (int e = 0; e < 27; e++) { float d = f[e] - mu; var += d * d; }
    var *= (1.0f / 27.0f);
    float rs = rsqrtf(var + 1e-5f);
    float h[28];
#pragma unroll
    for (int e = 0; e < 27; e++) h[e] = (f[e] - mu) * rs * s_g[e] + s_b[e];
    h[27] = 0.f;
    unsigned long long h2[14];
#pragma unroll
    for (int e = 0; e < 14; e++) h2[e] = pk2(h[2 * e], h[2 * e + 1]);

    const float scm = 0.17677669529663687f;
#pragma unroll
    for (int ph = 0; ph < 2; ph++) {
        unsigned long long wtx2[16];
#pragma unroll
        for (int m = 0; m < 16; m++) wtx2[m] = 0;
        float nrm = 0.f;
        for (int j = 0; j < 64; j++) {
            int row = ph * 64 + j;
            float acc = s_kb[row] + dot28(&s_kw[row * 28], h2);
            nrm += acc * acc;
            unsigned long long ad = pk2(acc, acc);
            const float* wr = &s_wT[j * MDIM];
#pragma unroll
            for (int m4 = 0; m4 < 8; m4++) {
                float4 wv = *(const float4*)&wr[m4 * 4];
                fma2(wtx2[m4 * 2],     ad, pk2(wv.x, wv.y));
                fma2(wtx2[m4 * 2 + 1], ad, pk2(wv.z, wv.w));
            }
        }
        float hn = 0.5f * nrm;
        float* outp = (ph == 0 ? g_kp1 : g_qp1) + (size_t)gt * MDIM;
#pragma unroll
        for (int m2 = 0; m2 < 16; m2++) {
            float2 p = upk(wtx2[m2]);
            outp[2 * m2]     = expf(p.x - hn) * scm;
            outp[2 * m2 + 1] = expf(p.y - hn) * scm;
        }
    }
    float* vout = g_v1 + (size_t)gt * EMB;
    for (int j = 0; j < 64; j++)
        vout[j] = s_kb[128 + j] + dot28(&s_kw[(128 + j) * 28], h2);
}

// ks[m] = sum_t kp[t][m]; kptv[n][m] = sum_t v[t][n]*kp[t][m]; 448 tokens/block
__global__ void __launch_bounds__(256) reduce_kernel(int stage, int T, int vstride)
{
    const float* kp = stage ? g_kp2 : g_kp1;
    const float* v  = stage ? (g_kqv2 + 128) : g_v1;
    float* ks   = stage ? g_ks2 : g_ks1;
    float* kptv = stage ? g_kptv2 : g_kptv1;

    __shared__ float s_kp[16 * MDIM];
    __shared__ float s_v [16 * EMB];
    int b = blockIdx.y, tid = threadIdx.x;
    int tok0 = blockIdx.x * 448;
    int n = tid >> 2, m0 = (tid & 3) * 8;
    float acc[8];
#pragma unroll
    for (int i = 0; i < 8; i++) acc[i] = 0.f;
    float ksacc = 0.f;
    const float* kpb = kp + ((size_t)b * T) * MDIM;
    const float* vb  = v  + ((size_t)b * T) * (size_t)vstride;
    for (int tile = 0; tile < 28; tile++) {
        int tb = tok0 + tile * 16;
        for (int i = tid; i < 16 * MDIM; i += 256)
            s_kp[i] = kpb[(size_t)tb * MDIM + i];
        for (int i = tid; i < 16 * EMB; i += 256) {
            int tt = i >> 6, nn = i & 63;
            s_v[i] = vb[(size_t)(tb + tt) * vstride + nn];
        }
        __syncthreads();
        if (tid < 32) {
#pragma unroll
            for (int tt = 0; tt < 16; tt++) ksacc += s_kp[tt * MDIM + tid];
        }
#pragma unroll 4
        for (int tt = 0; tt < 16; tt++) {
            float vv = s_v[tt * EMB + n];
#pragma unroll
            for (int i = 0; i < 8; i++) acc[i] += vv * s_kp[tt * MDIM + m0 + i];
        }
        __syncthreads();
    }
#pragma unroll
    for (int i = 0; i < 8; i++)
        atomicAdd(&kptv[b * EMB * MDIM + n * MDIM + m0 + i], acc[i]);
    if (tid < 32) atomicAdd(&ks[b * MDIM + tid], ksacc);
}

// performer epilogue: block-tiled GEMMs, f32x2-packed along token pairs
__global__ void __launch_bounds__(256) pass2_kernel(
    int stage, int T, int vstride,
    const float* __restrict__ pw, const float* __restrict__ pb,
    const float* __restrict__ g2v, const float* __restrict__ b2v,
    const float* __restrict__ m1w, const float* __restrict__ m1b,
    const float* __restrict__ m2w, const float* __restrict__ m2b)
{
    const float* qp   = stage ? g_qp2 : g_qp1;
    const float* v    = stage ? (g_kqv2 + 128) : g_v1;
    const float* ksg  = stage ? g_ks2 : g_ks1;
    const float* kptv = stage ? g_kptv2 : g_kptv1;
    float* xout       = stage ? g_x2 : g_x1;

    extern __shared__ float sm[];
    float* s_w1   = sm;
    float* s_w2   = sm + 4352;
    float* s_w3   = sm + 8704;
    float* s_kptv = sm + 13056;
    float* s_Q    = sm + 15232;
    float* s_V    = sm + 17344;
    float* s_X    = sm + 21696;
    float* s_ks   = sm + 25920;
    float* s_pb   = sm + 25952;
    float* s_g2   = sm + 26016;
    float* s_b2   = sm + 26080;
    float* s_m1b  = sm + 26144;
    float* s_m2b  = sm + 26208;

    int b = blockIdx.y, tid = threadIdx.x;
    int tx = tid & 15, ty = tid >> 4;
    int t0 = ty * 4, c0 = tx * 4;

    for (int idx = tid; idx < 4096; idx += 256) {
        int n = idx >> 6, j = idx & 63;
        s_w1[j * 68 + n] = pw [idx];
        s_w2[j * 68 + n] = m1w[idx];
        s_w3[j * 68 + n] = m2w[idx];
    }
    for (int idx = tid; idx < 2048; idx += 256) {
        int n = idx >> 5, m = idx & 31;
        s_kptv[m * 68 + n] = kptv[b * 2048 + idx];
    }
    if (tid < 32) s_ks[tid] = ksg[b * 32 + tid];
    if (tid < 64) {
        s_pb[tid] = pb[tid]; s_g2[tid] = g2v[tid]; s_b2[tid] = b2v[tid];
        s_m1b[tid] = m1b[tid]; s_m2b[tid] = m2b[tid];
    }
    __syncthreads();

    int nchunks = T >> 6;
    for (int chunk = blockIdx.x; chunk < nchunks; chunk += gridDim.x) {
        int tbase = chunk << 6;
        {
            const float* qb = qp + ((size_t)b * T + tbase) * MDIM;
            for (int idx = tid; idx < 2048; idx += 256) {
                int t = idx >> 5, m = idx & 31;
                s_Q[m * 66 + t] = qb[idx];
            }
        }
        {
            const float* vb = v + ((size_t)b * T + tbase) * (size_t)vstride;
            for (int idx = tid; idx < 1024; idx += 256) {
                int t = idx >> 4, cc = (idx & 15) * 4;
                float4 val = *(const float4*)&vb[(size_t)t * vstride + cc];
                *(float4*)&s_V[t * 68 + cc] = val;
            }
        }
        __syncthreads();

        unsigned long long a1acc[2][4], dv2[2];
        dv2[0] = dv2[1] = 0;
#pragma unroll
        for (int p = 0; p < 2; p++)
#pragma unroll
            for (int j = 0; j < 4; j++) a1acc[p][j] = 0;
#pragma unroll
        for (int kk = 0; kk < 32; kk++) {
            float2 a01 = *(const float2*)&s_Q[kk * 66 + t0];
            float2 a23 = *(const float2*)&s_Q[kk * 66 + t0 + 2];
            unsigned long long ap0 = pk2(a01.x, a01.y);
            unsigned long long ap1 = pk2(a23.x, a23.y);
            float4 bv = *(const float4*)&s_kptv[kk * 68 + c0];
            float kse = s_ks[kk];
            unsigned long long ksd = pk2(kse, kse);
            fma2(dv2[0], ap0, ksd); fma2(dv2[1], ap1, ksd);
            unsigned long long b0 = pk2(bv.x, bv.x), b1 = pk2(bv.y, bv.y);
            unsigned long long b2 = pk2(bv.z, bv.z), b3 = pk2(bv.w, bv.w);
            fma2(a1acc[0][0], ap0, b0); fma2(a1acc[0][1], ap0, b1);
            fma2(a1acc[0][2], ap0, b2); fma2(a1acc[0][3], ap0, b3);
            fma2(a1acc[1][0], ap1, b0); fma2(a1acc[1][1], ap1, b1);
            fma2(a1acc[1][2], ap1, b2); fma2(a1acc[1][3], ap1, b3);
        }
#pragma unroll
        for (int p = 0; p < 2; p++) {
            float2 dd = upk(dv2[p]);
            float inv0 = 1.0f / (dd.x + 1e-8f);
            float inv1 = 1.0f / (dd.y + 1e-8f);
#pragma unroll
            for (int j = 0; j < 4; j++) {
                float2 yy = upk(a1acc[p][j]);
                s_X[(c0 + j) * 66 + t0 + 2 * p]     = yy.x * inv0;
                s_X[(c0 + j) * 66 + t0 + 2 * p + 1] = yy.y * inv1;
            }
        }
        __syncthreads();

        unsigned long long o2[2][4];
#pragma unroll
        for (int p = 0; p < 2; p++)
#pragma unroll
            for (int j = 0; j < 4; j++)
                o2[p][j] = pk2(s_V[(t0 + 2 * p) * 68 + c0 + j] + s_pb[c0 + j],
                               s_V[(t0 + 2 * p + 1) * 68 + c0 + j] + s_pb[c0 + j]);
#pragma unroll
        for (int kk = 0; kk < 64; kk++) {
            float2 a01 = *(const float2*)&s_X[kk * 66 + t0];
            float2 a23 = *(const float2*)&s_X[kk * 66 + t0 + 2];
            unsigned long long ap0 = pk2(a01.x, a01.y);
            unsigned long long ap1 = pk2(a23.x, a23.y);
            float4 bv = *(const float4*)&s_w1[kk * 68 + c0];
            unsigned long long b0 = pk2(bv.x, bv.x), b1 = pk2(bv.y, bv.y);
            unsigned long long b2 = pk2(bv.z, bv.z), b3 = pk2(bv.w, bv.w);
            fma2(o2[0][0], ap0, b0); fma2(o2[0][1], ap0, b1);
            fma2(o2[0][2], ap0, b2); fma2(o2[0][3], ap0, b3);
            fma2(o2[1][0], ap1, b0); fma2(o2[1][1], ap1, b1);
            fma2(o2[1][2], ap1, b2); fma2(o2[1][3], ap1, b3);
        }
        float o[4][4];
#pragma unroll
        for (int p = 0; p < 2; p++)
#pragma unroll
            for (int j = 0; j < 4; j++) {
                float2 val = upk(o2[p][j]);
                o[2 * p][j] = val.x;
                o[2 * p + 1][j] = val.y;
            }
        float hh[4][4];
#pragma unroll
        for (int i = 0; i < 4; i++) {
            float s = red16(o[i][0] + o[i][1] + o[i][2] + o[i][3]);
            float mu = s * (1.0f / 64.0f);
            float d0 = o[i][0] - mu, d1 = o[i][1] - mu;
            float d2 = o[i][2] - mu, d3 = o[i][3] - mu;
            float vs = red16(d0 * d0 + d1 * d1 + d2 * d2 + d3 * d3);
            float rsl = rsqrtf(vs * (1.0f / 64.0f) + 1e-5f);
            hh[i][0] = d0 * rsl * s_g2[c0 + 0] + s_b2[c0 + 0];
            hh[i][1] = d1 * rsl * s_g2[c0 + 1] + s_b2[c0 + 1];
            hh[i][2] = d2 * rsl * s_g2[c0 + 2] + s_b2[c0 + 2];
            hh[i][3] = d3 * rsl * s_g2[c0 + 3] + s_b2[c0 + 3];
        }
        __syncthreads();
#pragma unroll
        for (int i = 0; i < 4; i++)
#pragma unroll
            for (int j = 0; j < 4; j++)
                s_X[(c0 + j) * 66 + t0 + i] = hh[i][j];
        __syncthreads();

        unsigned long long u2[2][4];
#pragma unroll
        for (int p = 0; p < 2; p++)
#pragma unroll
            for (int j = 0; j < 4; j++)
                u2[p][j] = pk2(s_m1b[c0 + j], s_m1b[c0 + j]);
#pragma unroll
        for (int kk = 0; kk < 64; kk++) {
            float2 a01 = *(const float2*)&s_X[kk * 66 + t0];
            float2 a23 = *(const float2*)&s_X[kk * 66 + t0 + 2];
            unsigned long long ap0 = pk2(a01.x, a01.y);
            unsigned long long ap1 = pk2(a23.x, a23.y);
            float4 bv = *(const float4*)&s_w2[kk * 68 + c0];
            unsigned long long b0 = pk2(bv.x, bv.x), b1 = pk2(bv.y, bv.y);
            unsigned long long b2 = pk2(bv.z, bv.z), b3 = pk2(bv.w, bv.w);
            fma2(u2[0][0], ap0, b0); fma2(u2[0][1], ap0, b1);
            fma2(u2[0][2], ap0, b2); fma2(u2[0][3], ap0, b3);
            fma2(u2[1][0], ap1, b0); fma2(u2[1][1], ap1, b1);
            fma2(u2[1][2], ap1, b2); fma2(u2[1][3], ap1, b3);
        }
        __syncthreads();
#pragma unroll
        for (int p = 0; p < 2; p++)
#pragma unroll
            for (int j = 0; j < 4; j++) {
                float2 uu = upk(u2[p][j]);
                float g0 = 0.5f * uu.x * (1.0f + erff(uu.x * 0.70710678118654752f));
                float g1 = 0.5f * uu.y * (1.0f + erff(uu.y * 0.70710678118654752f));
                s_X[(c0 + j) * 66 + t0 + 2 * p]     = g0;
                s_X[(c0 + j) * 66 + t0 + 2 * p + 1] = g1;
            }
        __syncthreads();

        unsigned long long r2[2][4];
#pragma unroll
        for (int p = 0; p < 2; p++)
#pragma unroll
            for (int j = 0; j < 4; j++)
                r2[p][j] = pk2(o[2 * p][j] + s_m2b[c0 + j],
                               o[2 * p + 1][j] + s_m2b[c0 + j]);
#pragma unroll
        for (int kk = 0; kk < 64; kk++) {
            float2 a01 = *(const float2*)&s_X[kk * 66 + t0];
            float2 a23 = *(const float2*)&s_X[kk * 66 + t0 + 2];
            unsigned long long ap0 = pk2(a01.x, a01.y);
            unsigned long long ap1 = pk2(a23.x, a23.y);
            float4 bv = *(const float4*)&s_w3[kk * 68 + c0];
            unsigned long long b0 = pk2(bv.x, bv.x), b1 = pk2(bv.y, bv.y);
            unsigned long long b2 = pk2(bv.z, bv.z), b3 = pk2(bv.w, bv.w);
            fma2(r2[0][0], ap0, b0); fma2(r2[0][1], ap0, b1);
            fma2(r2[0][2], ap0, b2); fma2(r2[0][3], ap0, b3);
            fma2(r2[1][0], ap1, b0); fma2(r2[1][1], ap1, b1);
            fma2(r2[1][2], ap1, b2); fma2(r2[1][3], ap1, b3);
        }
        __syncthreads();
#pragma unroll
        for (int p = 0; p < 2; p++)
#pragma unroll
            for (int j = 0; j < 4; j++) {
                float2 rr = upk(r2[p][j]);
                s_V[(c0 + j) * 68 + t0 + 2 * p]     = rr.x;
                s_V[(c0 + j) * 68 + t0 + 2 * p + 1] = rr.y;
            }
        __syncthreads();
        {
            float* xo = xout + (size_t)(b * 64) * T + tbase;
            for (int idx = tid; idx < 1024; idx += 256) {
                int cc = idx >> 4, t4 = (idx & 15) * 4;
                *(float4*)&xo[(size_t)cc * T + t4] = *(const float4*)&s_V[cc * 68 + t4];
            }
        }
        __syncthreads();
    }
}

// stage-2 tokens: unfold(s2 of x1) + LN(576) -> g_feat2 (warp per token)
__global__ void __launch_bounds__(256) feat2_kernel(
    const float* __restrict__ g, const float* __restrict__ bb)
{
    int tid = threadIdx.x, lane = tid & 31, wp = tid >> 5;
    int b = blockIdx.y;
    int t = blockIdx.x * 8 + wp;
    int i = t / 112, j = t - i * 112;
    const float* xb = g_x1 + (size_t)b * 64 * T1;
    float f[18];
    float s = 0.f, s2 = 0.f;
#pragma unroll
    for (int kk = 0; kk < 18; kk++) {
        int e = lane + 32 * kk;
        int c = e / 9; int r = e - c * 9; int kh = r / 3, kw = r - kh * 3;
        int yy = 2 * i + kh - 1, xx = 2 * j + kw - 1;
        float v = 0.f;
        if ((unsigned)yy < 224u && (unsigned)xx < 224u)
            v = xb[(size_t)c * T1 + yy * 224 + xx];
        f[kk] = v; s += v; s2 += v * v;
    }
    s  = warp_sum(s);
    s2 = warp_sum(s2);
    float mu = s * (1.0f / 576.0f);
    float var = s2 * (1.0f / 576.0f) - mu * mu;
    float rs = rsqrtf(var + 1e-5f);
    float* out = g_feat2 + ((size_t)b * T2 + t) * D2;
#pragma unroll
    for (int kk = 0; kk < 18; kk++) {
        int e = lane + 32 * kk;
        out[e] = (f[kk] - mu) * rs * g[e] + bb[e];
    }
}

// C[M,N] = A[M,K] @ W[N,K]^T + bias ; 128x64 tile, 8x4 micro, f32x2, k-tile 32
__global__ void __launch_bounds__(256) gemm_kernel(
    int which, const float* __restrict__ W, const float* __restrict__ bias,
    float* __restrict__ outp, int M, int N, int K)
{
    const float* A = which ? g_feat3 : g_feat2;
    float* C = which ? outp : g_kqv2;

    __shared__ float As[32][132];
    __shared__ float Bs[32][68];
    int m0 = blockIdx.x * 128, n0 = blockIdx.y * 64;
    int tid = threadIdx.x;
    int tx = tid & 15, ty = tid >> 4;
    int arow = tid >> 2;
    int kq = (tid & 3) * 4;

    const float* Ap = A + (size_t)(m0 + arow) * K + kq;
    const float* A2 = A + (size_t)(m0 + arow + 64) * K + kq;
    const float* Wp = W + (size_t)(n0 + arow) * K + kq;

    unsigned long long acc[4][4];
#pragma unroll
    for (int i = 0; i < 4; i++)
#pragma unroll
        for (int j = 0; j < 4; j++) acc[i][j] = 0;

    float4 av0a = *(const float4*)Ap;
    float4 av0b = *(const float4*)(Ap + 16);
    float4 av1a = *(const float4*)A2;
    float4 av1b = *(const float4*)(A2 + 16);
    float4 wva  = *(const float4*)Wp;
    float4 wvb  = *(const float4*)(Wp + 16);

    int nkt = K / 32;
    for (int kt = 0; kt < nkt; kt++) {
        As[kq + 0][arow] = av0a.x; As[kq + 1][arow] = av0a.y;
        As[kq + 2][arow] = av0a.z; As[kq + 3][arow] = av0a.w;
        As[kq + 16][arow] = av0b.x; As[kq + 17][arow] = av0b.y;
        As[kq + 18][arow] = av0b.z; As[kq + 19][arow] = av0b.w;
        As[kq + 0][arow + 64] = av1a.x; As[kq + 1][arow + 64] = av1a.y;
        As[kq + 2][arow + 64] = av1a.z; As[kq + 3][arow + 64] = av1a.w;
        As[kq + 16][arow + 64] = av1b.x; As[kq + 17][arow + 64] = av1b.y;
        As[kq + 18][arow + 64] = av1b.z; As[kq + 19][arow + 64] = av1b.w;
        Bs[kq + 0][arow] = wva.x; Bs[kq + 1][arow] = wva.y;
        Bs[kq + 2][arow] = wva.z; Bs[kq + 3][arow] = wva.w;
        Bs[kq + 16][arow] = wvb.x; Bs[kq + 17][arow] = wvb.y;
        Bs[kq + 18][arow] = wvb.z; Bs[kq + 19][arow] = wvb.w;
        __syncthreads();
        if (kt + 1 < nkt) {
            av0a = *(const float4*)(Ap + (kt + 1) * 32);
            av0b = *(const float4*)(Ap + (kt + 1) * 32 + 16);
            av1a = *(const float4*)(A2 + (kt + 1) * 32);
            av1b = *(const float4*)(A2 + (kt + 1) * 32 + 16);
            wva  = *(const float4*)(Wp + (kt + 1) * 32);
            wvb  = *(const float4*)(Wp + (kt + 1) * 32 + 16);
        }
#pragma unroll
        for (int kk = 0; kk < 32; kk++) {
            float4 a0 = *(const float4*)&As[kk][ty * 8];
            float4 a1 = *(const float4*)&As[kk][ty * 8 + 4];
            float4 b  = *(const float4*)&Bs[kk][tx * 4];
            unsigned long long ap[4] = {pk2(a0.x, a0.y), pk2(a0.z, a0.w),
                                        pk2(a1.x, a1.y), pk2(a1.z, a1.w)};
            unsigned long long bd[4] = {pk2(b.x, b.x), pk2(b.y, b.y),
                                        pk2(b.z, b.z), pk2(b.w, b.w)};
#pragma unroll
            for (int i = 0; i < 4; i++) {
                fma2(acc[i][0], ap[i], bd[0]);
                fma2(acc[i][1], ap[i], bd[1]);
                fma2(acc[i][2], ap[i], bd[2]);
                fma2(acc[i][3], ap[i], bd[3]);
            }
        }
        __syncthreads();
    }
    float4 bb = *(const float4*)&bias[n0 + tx * 4];
#pragma unroll
    for (int i = 0; i < 4; i++) {
        float2 c0 = upk(acc[i][0]);
        float2 c1 = upk(acc[i][1]);
        float2 c2 = upk(acc[i][2]);
        float2 c3 = upk(acc[i][3]);
        int row = m0 + ty * 8 + 2 * i;
        float4 lo = {c0.x + bb.x, c1.x + bb.y, c2.x + bb.z, c3.x + bb.w};
        float4 hi = {c0.y + bb.x, c1.y + bb.y, c2.y + bb.z, c3.y + bb.w};
        *(float4*)&C[(size_t)row * N + n0 + tx * 4] = lo;
        *(float4*)&C[(size_t)(row + 1) * N + n0 + tx * 4] = hi;
    }
}

// stage-2 phi from kqv2 (warp per token)
__global__ void __launch_bounds__(256) phi2_kernel(const float* __restrict__ w)
{
    __shared__ float s_wT[64 * MDIM];
    int tid = threadIdx.x, lane = tid & 31, wp = tid >> 5;
    for (int i = tid; i < 64 * MDIM; i += 256) {
        int j = i >> 5, m = i & 31;
        s_wT[i] = w[m * 64 + j];
    }
    __syncthreads();
    int t = blockIdx.x * 8 + wp;
    const float* base = g_kqv2 + (size_t)t * 192;
    const float scm = 0.17677669529663687f;
#pragma unroll
    for (int ph = 0; ph < 2; ph++) {
        float k0 = base[ph * 64 + lane];
        float k1 = base[ph * 64 + 32 + lane];
        float nrm = warp_sum(k0 * k0 + k1 * k1);
        float acc = 0.f;
#pragma unroll
        for (int s = 0; s < 32; s++) {
            float a = __shfl_sync(0xffffffffu, k0, s);
            float b = __shfl_sync(0xffffffffu, k1, s);
            acc += a * s_wT[s * MDIM + lane] + b * s_wT[(s + 32) * MDIM + lane];
        }
        float val = expf(acc - 0.5f * nrm) * scm;
        float* outp = (ph == 0 ? g_kp2 : g_qp2);
        outp[(size_t)t * MDIM + lane] = val;
    }
}

// stage-3 gather: unfold(s2 of x2) -> g_feat3
__global__ void __launch_bounds__(256) gather3_kernel()
{
    int idx = blockIdx.x * 256 + threadIdx.x;
    int e = idx % 576;
    int rest = idx / 576;
    int t = rest % T3;
    int b = rest / T3;
    int c = e / 9; int r = e - c * 9; int kh = r / 3, kw = r - kh * 3;
    int i = t / 56, j = t - i * 56;
    int yy = 2 * i + kh - 1, xx = 2 * j + kw - 1;
    float v = 0.f;
    if ((unsigned)yy < 112u && (unsigned)xx < 112u)
        v = g_x2[(size_t)(b * 64 + c) * T2 + yy * 112 + xx];
    g_feat3[idx] = v;
}

extern "C" void kernel_launch(void* const* d_in, const int* in_sizes, int n_in,
                              void* d_out, int out_size)
{
    cudaFuncSetAttribute(pass2_kernel,
                         cudaFuncAttributeMaxDynamicSharedMemorySize, 105088);

    const float* x        = (const float*)d_in[0];
    const float* p1_kqv_w = (const float*)d_in[1];
    const float* p1_kqv_b = (const float*)d_in[2];
    const float* p1_pw    = (const float*)d_in[3];
    const float* p1_pb    = (const float*)d_in[4];
    const float* p1_n1g   = (const float*)d_in[5];
    const float* p1_n1b   = (const float*)d_in[6];
    const float* p1_n2g   = (const float*)d_in[7];
    const float* p1_n2b   = (const float*)d_in[8];
    const float* p1_m1w   = (const float*)d_in[9];
    const float* p1_m1b   = (const float*)d_in[10];
    const float* p1_m2w   = (const float*)d_in[11];
    const float* p1_m2b   = (const float*)d_in[12];
    const float* p1_w     = (const float*)d_in[13];
    const float* p2_kqv_w = (const float*)d_in[14];
    const float* p2_kqv_b = (const float*)d_in[15];
    const float* p2_pw    = (const float*)d_in[16];
    const float* p2_pb    = (const float*)d_in[17];
    const float* p2_n1g   = (const float*)d_in[18];
    const float* p2_n1b   = (const float*)d_in[19];
    const float* p2_n2g   = (const float*)d_in[20];
    const float* p2_n2b   = (const float*)d_in[21];
    const float* p2_m1w   = (const float*)d_in[22];
    const float* p2_m1b   = (const float*)d_in[23];
    const float* p2_m2w   = (const float*)d_in[24];
    const float* p2_m2b   = (const float*)d_in[25];
    const float* p2_w     = (const float*)d_in[26];
    const float* proj_w   = (const float*)d_in[27];
    const float* proj_b   = (const float*)d_in[28];
    float* out = (float*)d_out;

    zero_red_kernel<<<64, 256>>>();

    // stage 1
    s1_pass1_kernel<<<BATCH * T1 / 128, 128>>>(x, p1_kqv_w, p1_kqv_b,
                                               p1_n1g, p1_n1b, p1_w);
    reduce_kernel<<<dim3(T1 / 448, BATCH), 256>>>(0, T1, EMB);
    pass2_kernel<<<dim3(98, BATCH), 256, 105088>>>(0, T1, EMB,
        p1_pw, p1_pb, p1_n2g, p1_n2b, p1_m1w, p1_m1b, p1_m2w, p1_m2b);

    // stage 2
    feat2_kernel<<<dim3(T2 / 8, BATCH), 256>>>(p2_n1g, p2_n1b);
    gemm_kernel<<<dim3((BATCH * T2) / 128, 192 / 64), 256>>>(
        0, p2_kqv_w, p2_kqv_b, nullptr, BATCH * T2, 192, D2);
    phi2_kernel<<<(BATCH * T2) / 8, 256>>>(p2_w);
    reduce_kernel<<<dim3(T2 / 448, BATCH), 256>>>(1, T2, 192);
    pass2_kernel<<<dim3(98, BATCH), 256, 105088>>>(1, T2, 192,
        p2_pw, p2_pb, p2_n2g, p2_n2b, p2_m1w, p2_m1b, p2_m2w, p2_m2b);

    // stage 3
    gather3_kernel<<<(BATCH * T3 * D2) / 256, 256>>>();
    gemm_kernel<<<dim3((BATCH * T3) / 128, 768 / 64), 256>>>(
        1, proj_w, proj_b, out, BATCH * T3, 768, D2);
}